// round 3
// baseline (speedup 1.0000x reference)
#include <cuda_runtime.h>
#include <cuda_bf16.h>

// ---------------------------------------------------------------------------
// Problem constants (fixed by the reference)
// ---------------------------------------------------------------------------
#define CLOUDS   4
#define NPTS     16384
#define MCENT    4096            // RATIO * NPTS
#define MAXNB    64
#define R2       0.0625f         // 0.25^2
#define CLUSTER  8
#define PTS_PER_CTA (NPTS / CLUSTER)   // 2048
#define FPS_THREADS 1024
#define PPT      2               // points per thread in FPS (2048/1024)

#define OUT_XC   0                      // x_centers  [16384*3]
#define OUT_POS  (CLOUDS*MCENT*3)       // pos[idx]   [16384*3]
#define OUT_BAT  (CLOUDS*MCENT*6)       // batch[idx] [16384]

// Device scratch (no cudaMalloc allowed)
__device__ float g_pos6[(size_t)CLOUDS * NPTS * 8];  // padded to 8 floats/pt
__device__ int   g_idx[CLOUDS * MCENT];

// ---------------------------------------------------------------------------
// 6-D squared distance, FMA left fold — matches XLA:GPU contraction of
// sum((p-c)**2, axis=-1):  d = t0*t0; d = fma(t,t,d) for t1..t5
// ---------------------------------------------------------------------------
__device__ __forceinline__ float dist6(float p0, float p1, float p2,
                                       float p3, float p4, float p5,
                                       float c0, float c1, float c2,
                                       float c3, float c4, float c5) {
    float t, d;
    t = __fsub_rn(p0, c0); d = __fmul_rn(t, t);
    t = __fsub_rn(p1, c1); d = __fmaf_rn(t, t, d);
    t = __fsub_rn(p2, c2); d = __fmaf_rn(t, t, d);
    t = __fsub_rn(p3, c3); d = __fmaf_rn(t, t, d);
    t = __fsub_rn(p4, c4); d = __fmaf_rn(t, t, d);
    t = __fsub_rn(p5, c5); d = __fmaf_rn(t, t, d);
    return d;
}

__device__ __forceinline__ unsigned long long packkey(float key, unsigned lidx) {
    // keys are finite & non-negative -> float bits order-preserving.
    // invert idx so u64-max picks the SMALLEST index on key ties (jnp.argmax).
    return ((unsigned long long)__float_as_uint(key) << 32) |
           (unsigned long long)(0xFFFFFFFFu - lidx);
}
__device__ __forceinline__ unsigned long long u64max(unsigned long long a,
                                                     unsigned long long b) {
    return a > b ? a : b;
}

// ---------------------------------------------------------------------------
// Kernel A: build padded pos6 = [x0 x1 x2 p0 p1 p2 0 0] per point
// ---------------------------------------------------------------------------
__global__ void prep_kernel(const float* __restrict__ x,
                            const float* __restrict__ pos) {
    int i = blockIdx.x * blockDim.x + threadIdx.x;
    if (i >= CLOUDS * NPTS) return;
    float4 r0 = make_float4(x[3 * i], x[3 * i + 1], x[3 * i + 2], pos[3 * i]);
    float4 r1 = make_float4(pos[3 * i + 1], pos[3 * i + 2], 0.f, 0.f);
    float4* dst = reinterpret_cast<float4*>(g_pos6);
    dst[2 * i] = r0;
    dst[2 * i + 1] = r1;
}

// ---------------------------------------------------------------------------
// Kernel B: FPS.  One 8-CTA cluster per cloud, 1024 threads/CTA, 2 pts/thread.
// Per round: local update+argmax -> CTA candidate -> cluster barrier ->
// DSMEM candidate exchange -> winner coords broadcast.
// ---------------------------------------------------------------------------
struct FpsShm {
    unsigned long long warpbest[32];
    unsigned long long candkey[2];    // double-buffered by iteration parity
    float4 candc[2][2];
    float4 wc[2];                     // winner coords broadcast
    float4 pts[PTS_PER_CTA * 2];      // local copy of this CTA's points
};

__global__ void __cluster_dims__(CLUSTER, 1, 1) __launch_bounds__(FPS_THREADS, 1)
fps_kernel() {
    extern __shared__ unsigned char smraw[];
    FpsShm* sh = reinterpret_cast<FpsShm*>(smraw);

    const int cloud = blockIdx.x / CLUSTER;
    const unsigned rank = blockIdx.x % CLUSTER;
    const int tid = threadIdx.x;
    const int wid = tid >> 5;
    const int lane = tid & 31;

    const float4* gp = reinterpret_cast<const float4*>(
        g_pos6 + (size_t)cloud * NPTS * 8);

    // Load my 2 points into registers and the CTA smem copy.
    const int off = 2 * tid;                        // local offset in CTA
    const int lp0 = rank * PTS_PER_CTA + off;       // local idx within cloud
    float4 a0 = gp[2 * lp0],     a1 = gp[2 * lp0 + 1];
    float4 b0 = gp[2 * lp0 + 2], b1 = gp[2 * lp0 + 3];
    sh->pts[2 * off]     = a0;  sh->pts[2 * off + 1] = a1;
    sh->pts[2 * off + 2] = b0;  sh->pts[2 * off + 3] = b1;

    float mind0 = __int_as_float(0x7f800000);   // +inf
    float mind1 = __int_as_float(0x7f800000);

    if (tid == 0) {
        sh->wc[0] = gp[0];                      // pick 0 = point 0
        sh->wc[1] = gp[1];
        if (rank == 0) g_idx[cloud * MCENT] = cloud * NPTS;
    }
    __syncthreads();

#pragma unroll 1
    for (int k = 1; k < MCENT; ++k) {
        const int par = k & 1;
        // ---- update mind with distance to current pick; local argmax ----
        float4 w0 = sh->wc[0], w1 = sh->wc[1];
        float d0 = dist6(a0.x, a0.y, a0.z, a0.w, a1.x, a1.y,
                         w0.x, w0.y, w0.z, w0.w, w1.x, w1.y);
        float d1 = dist6(b0.x, b0.y, b0.z, b0.w, b1.x, b1.y,
                         w0.x, w0.y, w0.z, w0.w, w1.x, w1.y);
        mind0 = fminf(mind0, d0);
        mind1 = fminf(mind1, d1);
        unsigned long long best =
            u64max(packkey(mind0, (unsigned)lp0), packkey(mind1, (unsigned)(lp0 + 1)));
#pragma unroll
        for (int s = 16; s > 0; s >>= 1)
            best = u64max(best, __shfl_down_sync(0xffffffffu, best, s));
        if (lane == 0) sh->warpbest[wid] = best;
        __syncthreads();

        if (wid == 0) {
            unsigned long long b = sh->warpbest[lane];
#pragma unroll
            for (int s = 16; s > 0; s >>= 1)
                b = u64max(b, __shfl_down_sync(0xffffffffu, b, s));
            if (lane == 0) {
                unsigned lidx = 0xFFFFFFFFu - (unsigned)(b & 0xFFFFFFFFull);
                int loc = (int)lidx - (int)rank * PTS_PER_CTA;
                sh->candkey[par]  = b;
                sh->candc[par][0] = sh->pts[2 * loc];
                sh->candc[par][1] = sh->pts[2 * loc + 1];
            }
        }
        // candidate visible cluster-wide after arrive(release)/wait(acquire)
        asm volatile("barrier.cluster.arrive.aligned;" ::: "memory");
        asm volatile("barrier.cluster.wait.aligned;"   ::: "memory");

        // ---- resolve cluster winner (warp 0, lanes 0..7) ----
        if (wid == 0 && lane < CLUSTER) {
            unsigned lk = (unsigned)__cvta_generic_to_shared(&sh->candkey[par]);
            unsigned lc = (unsigned)__cvta_generic_to_shared(&sh->candc[par][0]);
            unsigned rk, rc;
            asm("mapa.shared::cluster.u32 %0, %1, %2;" : "=r"(rk) : "r"(lk), "r"(lane));
            asm("mapa.shared::cluster.u32 %0, %1, %2;" : "=r"(rc) : "r"(lc), "r"(lane));
            unsigned long long key;
            float4 c0, c1;
            asm volatile("ld.shared::cluster.b64 %0, [%1];" : "=l"(key) : "r"(rk));
            asm volatile("ld.shared::cluster.v4.f32 {%0,%1,%2,%3}, [%4];"
                         : "=f"(c0.x), "=f"(c0.y), "=f"(c0.z), "=f"(c0.w) : "r"(rc));
            asm volatile("ld.shared::cluster.v4.f32 {%0,%1,%2,%3}, [%4];"
                         : "=f"(c1.x), "=f"(c1.y), "=f"(c1.z), "=f"(c1.w)
                         : "r"(rc + 16));
            unsigned long long mx = key;
            mx = u64max(mx, __shfl_xor_sync(0xFFu, mx, 1));
            mx = u64max(mx, __shfl_xor_sync(0xFFu, mx, 2));
            mx = u64max(mx, __shfl_xor_sync(0xFFu, mx, 4));
            if (key == mx) {            // unique (idx packed -> distinct keys)
                sh->wc[0] = c0;
                sh->wc[1] = c1;
            }
            if (lane == 0 && rank == 0) {
                unsigned lidx = 0xFFFFFFFFu - (unsigned)(mx & 0xFFFFFFFFull);
                g_idx[cloud * MCENT + k] = cloud * NPTS + (int)lidx;
            }
        }
        __syncthreads();   // wc ready for next round
    }
}

// ---------------------------------------------------------------------------
// Kernel C: radius neighbors + mean.  One warp per center; ordered first-64
// take via ballot so capping matches torch_cluster/top_k semantics exactly.
// ---------------------------------------------------------------------------
__global__ void __launch_bounds__(256)
nbr_kernel(float* __restrict__ out, int out_size) {
    int w = (blockIdx.x * blockDim.x + threadIdx.x) >> 5;
    int lane = threadIdx.x & 31;
    if (w >= CLOUDS * MCENT) return;
    int cloud = w >> 12;                 // 4096 centers per cloud
    int g = g_idx[w];
    int lc = g - cloud * NPTS;

    const float4* gp = reinterpret_cast<const float4*>(
        g_pos6 + (size_t)cloud * NPTS * 8);
    float4 c0 = gp[2 * lc], c1 = gp[2 * lc + 1];

    float sx = 0.f, sy = 0.f, sz = 0.f;
    int cnt = 0;
    for (int base = 0; base < NPTS; base += 32) {
        int i = base + lane;
        float4 a0 = gp[2 * i], a1 = gp[2 * i + 1];
        float d = dist6(a0.x, a0.y, a0.z, a0.w, a1.x, a1.y,
                        c0.x, c0.y, c0.z, c0.w, c1.x, c1.y);
        bool pred = (d <= R2);
        unsigned mask = __ballot_sync(0xffffffffu, pred);
        int need = MAXNB - cnt;
        int rk = __popc(mask & ((1u << lane) - 1u));
        if (pred && rk < need) { sx += a0.x; sy += a0.y; sz += a0.z; }
        int c = __popc(mask);
        cnt += (c < need) ? c : need;
        if (cnt >= MAXNB) break;         // warp-uniform
    }
#pragma unroll
    for (int s = 16; s > 0; s >>= 1) {
        sx += __shfl_down_sync(0xffffffffu, sx, s);
        sy += __shfl_down_sync(0xffffffffu, sy, s);
        sz += __shfl_down_sync(0xffffffffu, sz, s);
    }
    if (lane == 0) {
        float c = (float)cnt;            // self always in radius -> cnt >= 1
        if (OUT_XC + w * 3 + 2 < out_size) {
            out[OUT_XC + w * 3 + 0] = sx / c;
            out[OUT_XC + w * 3 + 1] = sy / c;
            out[OUT_XC + w * 3 + 2] = sz / c;
        }
    }
}

// ---------------------------------------------------------------------------
// Kernel D: gather pos[idx] and batch[idx]
// ---------------------------------------------------------------------------
__global__ void sample_kernel(const float* __restrict__ pos,
                              float* __restrict__ out, int out_size) {
    int c = blockIdx.x * blockDim.x + threadIdx.x;
    if (c >= CLOUDS * MCENT) return;
    int g = g_idx[c];
    if (OUT_POS + c * 3 + 2 < out_size) {
        out[OUT_POS + c * 3 + 0] = pos[3 * g + 0];
        out[OUT_POS + c * 3 + 1] = pos[3 * g + 1];
        out[OUT_POS + c * 3 + 2] = pos[3 * g + 2];
    }
    if (OUT_BAT + c < out_size)
        out[OUT_BAT + c] = (float)(g >> 14);   // batch id = g / NPTS
}

// ---------------------------------------------------------------------------
extern "C" void kernel_launch(void* const* d_in, const int* in_sizes, int n_in,
                              void* d_out, int out_size) {
    const float* x   = (const float*)d_in[0];
    const float* pos = (const float*)d_in[1];
    float* out = (float*)d_out;

    cudaFuncSetAttribute(fps_kernel,
                         cudaFuncAttributeMaxDynamicSharedMemorySize,
                         (int)sizeof(FpsShm));

    prep_kernel<<<(CLOUDS * NPTS + 255) / 256, 256>>>(x, pos);
    fps_kernel<<<CLOUDS * CLUSTER, FPS_THREADS, sizeof(FpsShm)>>>();
    nbr_kernel<<<(CLOUDS * MCENT * 32) / 256, 256>>>(out, out_size);
    sample_kernel<<<(CLOUDS * MCENT + 255) / 256, 256>>>(pos, out, out_size);
}

// round 4
// speedup vs baseline: 1.4845x; 1.4845x over previous
#include <cuda_runtime.h>
#include <cuda_bf16.h>

// ---------------------------------------------------------------------------
// Problem constants (fixed by the reference)
// ---------------------------------------------------------------------------
#define CLOUDS   4
#define NPTS     16384
#define MCENT    4096            // RATIO * NPTS
#define MAXNB    64
#define R2       0.0625f         // 0.25^2
#define CLUSTER  8
#define PTS_PER_CTA (NPTS / CLUSTER)   // 2048
#define FPS_THREADS 1024

#define OUT_XC   0                      // x_centers  [16384*3]
#define OUT_POS  (CLOUDS*MCENT*3)       // pos[idx]   [16384*3]
#define OUT_BAT  (CLOUDS*MCENT*6)       // batch[idx] [16384]

// Device scratch (no cudaMalloc allowed)
__device__ float g_pos6[(size_t)CLOUDS * NPTS * 8];  // padded to 8 floats/pt
__device__ int   g_idx[CLOUDS * MCENT];

// ---------------------------------------------------------------------------
// 6-D squared distance, FMA left fold — matches XLA:GPU contraction of
// sum((p-c)**2, axis=-1):  d = t0*t0; d = fma(t,t,d) for t1..t5
// ---------------------------------------------------------------------------
__device__ __forceinline__ float dist6(float p0, float p1, float p2,
                                       float p3, float p4, float p5,
                                       float c0, float c1, float c2,
                                       float c3, float c4, float c5) {
    float t, d;
    t = __fsub_rn(p0, c0); d = __fmul_rn(t, t);
    t = __fsub_rn(p1, c1); d = __fmaf_rn(t, t, d);
    t = __fsub_rn(p2, c2); d = __fmaf_rn(t, t, d);
    t = __fsub_rn(p3, c3); d = __fmaf_rn(t, t, d);
    t = __fsub_rn(p4, c4); d = __fmaf_rn(t, t, d);
    t = __fsub_rn(p5, c5); d = __fmaf_rn(t, t, d);
    return d;
}

__device__ __forceinline__ unsigned redux_max_u32(unsigned v, unsigned mask) {
    unsigned r;
    asm("redux.sync.max.u32 %0, %1, %2;" : "=r"(r) : "r"(v), "r"(mask));
    return r;
}

// ---------------------------------------------------------------------------
// Kernel A: build padded pos6 = [x0 x1 x2 p0 p1 p2 0 0] per point
// ---------------------------------------------------------------------------
__global__ void prep_kernel(const float* __restrict__ x,
                            const float* __restrict__ pos) {
    int i = blockIdx.x * blockDim.x + threadIdx.x;
    if (i >= CLOUDS * NPTS) return;
    float4 r0 = make_float4(x[3 * i], x[3 * i + 1], x[3 * i + 2], pos[3 * i]);
    float4 r1 = make_float4(pos[3 * i + 1], pos[3 * i + 2], 0.f, 0.f);
    float4* dst = reinterpret_cast<float4*>(g_pos6);
    dst[2 * i] = r0;
    dst[2 * i + 1] = r1;
}

// ---------------------------------------------------------------------------
// Kernel B: FPS v2. One 8-CTA cluster per cloud, 1024 thr/CTA, 2 pts/thread.
// Exchange via st.async + mbarrier (no cluster barrier in the loop).
// Candidate record = 8 u32: {keybits, local_idx, c0,c1,c2,c3,c4,c5}.
// ---------------------------------------------------------------------------
__global__ void __cluster_dims__(CLUSTER, 1, 1) __launch_bounds__(FPS_THREADS, 1)
fps_kernel() {
    __shared__ unsigned long long mbar[2];
    __shared__ uint4 candbuf[2][CLUSTER][2];   // [parity][sender rank][32B]
    __shared__ unsigned slotkey[32];           // per-warp winner keybits
    __shared__ uint4 slotc[32][2];             // per-warp winner record
    __shared__ uint4 wc[2];                    // cluster winner record

    const int cloud = blockIdx.x / CLUSTER;
    const unsigned rank = blockIdx.x % CLUSTER;
    const int tid = threadIdx.x;
    const int wid = tid >> 5;
    const int lane = tid & 31;

    const float4* gp = reinterpret_cast<const float4*>(
        g_pos6 + (size_t)cloud * NPTS * 8);

    const int lp0 = (int)rank * PTS_PER_CTA + 2 * tid;   // cloud-local idx
    float4 a0 = gp[2 * lp0],     a1 = gp[2 * lp0 + 1];
    float4 b0 = gp[2 * lp0 + 2], b1 = gp[2 * lp0 + 3];

    if (tid == 0) {
        // init both mbarriers with arrive count = 1 (leader's arrive.expect_tx)
        unsigned m0 = (unsigned)__cvta_generic_to_shared(&mbar[0]);
        unsigned m1 = (unsigned)__cvta_generic_to_shared(&mbar[1]);
        asm volatile("mbarrier.init.shared.b64 [%0], 1;" :: "r"(m0) : "memory");
        asm volatile("mbarrier.init.shared.b64 [%0], 1;" :: "r"(m1) : "memory");
        asm volatile("fence.mbarrier_init.release.cluster;" ::: "memory");
        // pick 0 = point 0 of the cloud
        float4 p0 = gp[0], p1 = gp[1];
        wc[0] = make_uint4(0u, 0u, __float_as_uint(p0.x), __float_as_uint(p0.y));
        wc[1] = make_uint4(__float_as_uint(p0.z), __float_as_uint(p0.w),
                           __float_as_uint(p1.x), __float_as_uint(p1.y));
        if (rank == 0) g_idx[cloud * MCENT] = cloud * NPTS;
    }
    __syncthreads();
    // make mbarrier init visible cluster-wide before any peer st.async
    asm volatile("barrier.cluster.arrive.aligned;" ::: "memory");
    asm volatile("barrier.cluster.wait.aligned;"   ::: "memory");

    float mind0 = __int_as_float(0x7f800000);
    float mind1 = __int_as_float(0x7f800000);
    int ph0 = 0, ph1 = 0;

#pragma unroll 1
    for (int k = 1; k < MCENT; ++k) {
        const int par = k & 1;
        // ---- distance to current winner, update mind, thread-best ----
        uint4 w0u = wc[0], w1u = wc[1];
        float w0 = __uint_as_float(w0u.z), w1 = __uint_as_float(w0u.w);
        float w2 = __uint_as_float(w1u.x), w3 = __uint_as_float(w1u.y);
        float w4 = __uint_as_float(w1u.z), w5 = __uint_as_float(w1u.w);
        float d0 = dist6(a0.x, a0.y, a0.z, a0.w, a1.x, a1.y,
                         w0, w1, w2, w3, w4, w5);
        float d1 = dist6(b0.x, b0.y, b0.z, b0.w, b1.x, b1.y,
                         w0, w1, w2, w3, w4, w5);
        mind0 = fminf(mind0, d0);
        mind1 = fminf(mind1, d1);
        unsigned kb0 = __float_as_uint(mind0);
        unsigned kb1 = __float_as_uint(mind1);
        bool t1 = kb1 > kb0;                 // tie -> pt0 (smaller idx)
        unsigned kb = t1 ? kb1 : kb0;
        unsigned myidx = (unsigned)lp0 + (t1 ? 1u : 0u);

        // ---- warp argmax: redux + ballot (lowest lane = lowest idx) ----
        unsigned m = redux_max_u32(kb, 0xffffffffu);
        unsigned bal = __ballot_sync(0xffffffffu, kb == m);
        if (lane == __ffs(bal) - 1) {
            float4 cc0 = t1 ? b0 : a0;
            float4 cc1 = t1 ? b1 : a1;
            slotkey[wid] = m;
            slotc[wid][0] = make_uint4(m, myidx,
                                       __float_as_uint(cc0.x),
                                       __float_as_uint(cc0.y));
            slotc[wid][1] = make_uint4(__float_as_uint(cc0.z),
                                       __float_as_uint(cc0.w),
                                       __float_as_uint(cc1.x),
                                       __float_as_uint(cc1.y));
        }
        if (tid == 0) {   // expected tx: 8 senders x 32 bytes
            unsigned mb = (unsigned)__cvta_generic_to_shared(&mbar[par]);
            asm volatile("mbarrier.arrive.expect_tx.shared.b64 _, [%0], %1;"
                         :: "r"(mb), "r"(256u) : "memory");
        }
        __syncthreads();

        if (wid == 0) {
            // ---- CTA argmax over 32 warp slots (lane order = idx order) ----
            unsigned kw = slotkey[lane];
            unsigned M = redux_max_u32(kw, 0xffffffffu);
            unsigned bb = __ballot_sync(0xffffffffu, kw == M);
            int s = __ffs(bb) - 1;
            if (lane < CLUSTER) {
                // ship CTA candidate (32B) to peer CTA 'lane', slot = my rank
                unsigned long long q0, q1, q2, q3;
                const unsigned long long* src =
                    reinterpret_cast<const unsigned long long*>(&slotc[s][0]);
                q0 = src[0]; q1 = src[1]; q2 = src[2]; q3 = src[3];
                unsigned dl = (unsigned)__cvta_generic_to_shared(
                    &candbuf[par][rank][0]);
                unsigned ml = (unsigned)__cvta_generic_to_shared(&mbar[par]);
                unsigned dr, mr;
                asm("mapa.shared::cluster.u32 %0, %1, %2;"
                    : "=r"(dr) : "r"(dl), "r"(lane));
                asm("mapa.shared::cluster.u32 %0, %1, %2;"
                    : "=r"(mr) : "r"(ml), "r"(lane));
                asm volatile(
                    "st.async.shared::cluster.mbarrier::complete_tx::bytes.b64 [%0], %1, [%2];"
                    :: "r"(dr), "l"(q0), "r"(mr) : "memory");
                asm volatile(
                    "st.async.shared::cluster.mbarrier::complete_tx::bytes.b64 [%0], %1, [%2];"
                    :: "r"(dr + 8), "l"(q1), "r"(mr) : "memory");
                asm volatile(
                    "st.async.shared::cluster.mbarrier::complete_tx::bytes.b64 [%0], %1, [%2];"
                    :: "r"(dr + 16), "l"(q2), "r"(mr) : "memory");
                asm volatile(
                    "st.async.shared::cluster.mbarrier::complete_tx::bytes.b64 [%0], %1, [%2];"
                    :: "r"(dr + 24), "l"(q3), "r"(mr) : "memory");
            }
            // ---- wait for all 8 candidates (warp0 only) ----
            {
                unsigned mb = (unsigned)__cvta_generic_to_shared(&mbar[par]);
                int ph = par ? ph1 : ph0;
                unsigned done = 0;
                do {
                    asm volatile(
                        "{ .reg .pred p;\n\t"
                        "mbarrier.try_wait.parity.acquire.cluster.shared::cta.b64 p, [%1], %2, 0x989680;\n\t"
                        "selp.b32 %0, 1, 0, p; }"
                        : "=r"(done) : "r"(mb), "r"((unsigned)ph) : "memory");
                } while (!done);
                if (par) ph1 ^= 1; else ph0 ^= 1;
            }
            // ---- cluster argmax over 8 candidates (rank order = idx order) --
            if (lane < CLUSTER) {
                unsigned kc = candbuf[par][lane][0].x;
                unsigned M2 = redux_max_u32(kc, 0xFFu);
                unsigned b2 = __ballot_sync(0xFFu, kc == M2);
                int s2 = __ffs(b2) - 1;
                if (lane == 0) {
                    uint4 c0 = candbuf[par][s2][0];
                    uint4 c1 = candbuf[par][s2][1];
                    wc[0] = c0;
                    wc[1] = c1;
                    if (rank == 0)
                        g_idx[cloud * MCENT + k] = cloud * NPTS + (int)c0.y;
                }
            }
        }
        __syncthreads();   // wc ready for next round
    }
}

// ---------------------------------------------------------------------------
// Kernel C: radius neighbors + mean.  One warp per center; ordered first-64
// take via ballot so capping matches top_k-on-index semantics exactly.
// ---------------------------------------------------------------------------
__global__ void __launch_bounds__(256)
nbr_kernel(float* __restrict__ out, int out_size) {
    int w = (blockIdx.x * blockDim.x + threadIdx.x) >> 5;
    int lane = threadIdx.x & 31;
    if (w >= CLOUDS * MCENT) return;
    int cloud = w >> 12;                 // 4096 centers per cloud
    int g = g_idx[w];
    int lc = g - cloud * NPTS;

    const float4* gp = reinterpret_cast<const float4*>(
        g_pos6 + (size_t)cloud * NPTS * 8);
    float4 c0 = gp[2 * lc], c1 = gp[2 * lc + 1];

    float sx = 0.f, sy = 0.f, sz = 0.f;
    int cnt = 0;
    for (int base = 0; base < NPTS; base += 32) {
        int i = base + lane;
        float4 a0 = gp[2 * i], a1 = gp[2 * i + 1];
        float d = dist6(a0.x, a0.y, a0.z, a0.w, a1.x, a1.y,
                        c0.x, c0.y, c0.z, c0.w, c1.x, c1.y);
        bool pred = (d <= R2);
        unsigned mask = __ballot_sync(0xffffffffu, pred);
        int need = MAXNB - cnt;
        int rk = __popc(mask & ((1u << lane) - 1u));
        if (pred && rk < need) { sx += a0.x; sy += a0.y; sz += a0.z; }
        int c = __popc(mask);
        cnt += (c < need) ? c : need;
        if (cnt >= MAXNB) break;         // warp-uniform
    }
#pragma unroll
    for (int s = 16; s > 0; s >>= 1) {
        sx += __shfl_down_sync(0xffffffffu, sx, s);
        sy += __shfl_down_sync(0xffffffffu, sy, s);
        sz += __shfl_down_sync(0xffffffffu, sz, s);
    }
    if (lane == 0) {
        float c = (float)cnt;            // self always in radius -> cnt >= 1
        if (OUT_XC + w * 3 + 2 < out_size) {
            out[OUT_XC + w * 3 + 0] = sx / c;
            out[OUT_XC + w * 3 + 1] = sy / c;
            out[OUT_XC + w * 3 + 2] = sz / c;
        }
    }
}

// ---------------------------------------------------------------------------
// Kernel D: gather pos[idx] and batch[idx]
// ---------------------------------------------------------------------------
__global__ void sample_kernel(const float* __restrict__ pos,
                              float* __restrict__ out, int out_size) {
    int c = blockIdx.x * blockDim.x + threadIdx.x;
    if (c >= CLOUDS * MCENT) return;
    int g = g_idx[c];
    if (OUT_POS + c * 3 + 2 < out_size) {
        out[OUT_POS + c * 3 + 0] = pos[3 * g + 0];
        out[OUT_POS + c * 3 + 1] = pos[3 * g + 1];
        out[OUT_POS + c * 3 + 2] = pos[3 * g + 2];
    }
    if (OUT_BAT + c < out_size)
        out[OUT_BAT + c] = (float)(g >> 14);   // batch id = g / NPTS
}

// ---------------------------------------------------------------------------
extern "C" void kernel_launch(void* const* d_in, const int* in_sizes, int n_in,
                              void* d_out, int out_size) {
    const float* x   = (const float*)d_in[0];
    const float* pos = (const float*)d_in[1];
    float* out = (float*)d_out;

    prep_kernel<<<(CLOUDS * NPTS + 255) / 256, 256>>>(x, pos);
    fps_kernel<<<CLOUDS * CLUSTER, FPS_THREADS>>>();
    nbr_kernel<<<(CLOUDS * MCENT * 32) / 256, 256>>>(out, out_size);
    sample_kernel<<<(CLOUDS * MCENT + 255) / 256, 256>>>(pos, out, out_size);
}